// round 2
// baseline (speedup 1.0000x reference)
#include <cuda_runtime.h>
#include <math.h>

// ---------------- problem constants ----------------
#define LSEQ   1024
#define DM     768
#define EINNER 1536
#define NSTATE 16
#define DTR    48
#define VOC    50257
#define PROJW  80          // DTR + 2*NSTATE
#define NCHUNK 16
#define CLEN   64          // LSEQ / NCHUNK
#define NLAYER 4

// ---------------- scratch (static device globals; no allocation) ----------------
__device__ float g_h   [LSEQ * DM];
__device__ float g_hn  [LSEQ * DM];
__device__ float g_xz  [LSEQ * 2 * EINNER];
__device__ float g_xc  [LSEQ * EINNER];
__device__ float g_proj[LSEQ * PROJW];
__device__ float g_dt  [LSEQ * EINNER];
__device__ float g_y   [LSEQ * EINNER];
__device__ float g_cA  [NCHUNK * EINNER * NSTATE];
__device__ float g_cB  [NCHUNK * EINNER * NSTATE];
__device__ float g_ini [NCHUNK * EINNER * NSTATE];
__device__ float g_Aneg[EINNER * NSTATE];      // -exp(A_log) for current layer

// ---------------- embedding gather ----------------
__global__ void k_embed(const int* __restrict__ x, const float* __restrict__ embed) {
    int l = blockIdx.x;
    int t = x[l];
    for (int d = threadIdx.x; d < DM; d += blockDim.x)
        g_h[l * DM + d] = embed[(size_t)t * DM + d];
}

// ---------------- rmsnorm: g_hn = rmsnorm(g_h, w) ----------------
__global__ void k_rmsnorm(const float* __restrict__ w) {
    __shared__ float red[8];
    int l = blockIdx.x;
    float s = 0.f;
    for (int d = threadIdx.x; d < DM; d += 256) {
        float v = g_h[l * DM + d];
        s += v * v;
    }
    #pragma unroll
    for (int o = 16; o; o >>= 1) s += __shfl_xor_sync(0xffffffffu, s, o);
    if ((threadIdx.x & 31) == 0) red[threadIdx.x >> 5] = s;
    __syncthreads();
    if (threadIdx.x == 0) {
        float t = 0.f;
        #pragma unroll
        for (int i = 0; i < 8; i++) t += red[i];
        red[0] = rsqrtf(t / DM + 1e-5f);
    }
    __syncthreads();
    float r = red[0];
    for (int d = threadIdx.x; d < DM; d += 256)
        g_hn[l * DM + d] = g_h[l * DM + d] * r * w[d];
}

// ---------------- SGEMM: C[M,N] (+)= A[M,K] * B[N,K]^T ----------------
// 128x128 block tile, 8-deep k tile, 256 threads, 8x8 per thread.
// Requires K % 8 == 0 and 16B-aligned A/B rows (true: K in {768,1536}).
template<bool ACC>
__global__ void __launch_bounds__(256, 2)
k_sgemm(const float* __restrict__ A, const float* __restrict__ B,
        float* __restrict__ C, int M, int N, int K) {
    __shared__ float As[8][128];
    __shared__ float Bs[8][128];
    int tid = threadIdx.x;
    int tx = tid & 15, ty = tid >> 4;
    int m0 = blockIdx.y * 128, n0 = blockIdx.x * 128;
    int lr = tid >> 1;            // 0..127: row within tile
    int lk = (tid & 1) * 4;       // 0 or 4 : k within tile

    float acc[8][8];
    #pragma unroll
    for (int i = 0; i < 8; i++)
        #pragma unroll
        for (int j = 0; j < 8; j++) acc[i][j] = 0.f;

    for (int k0 = 0; k0 < K; k0 += 8) {
        float4 va = make_float4(0.f, 0.f, 0.f, 0.f);
        float4 vb = make_float4(0.f, 0.f, 0.f, 0.f);
        int gm = m0 + lr;
        int gn = n0 + lr;
        if (gm < M) va = *(const float4*)(A + (size_t)gm * K + k0 + lk);
        if (gn < N) vb = *(const float4*)(B + (size_t)gn * K + k0 + lk);
        As[lk + 0][lr] = va.x; As[lk + 1][lr] = va.y;
        As[lk + 2][lr] = va.z; As[lk + 3][lr] = va.w;
        Bs[lk + 0][lr] = vb.x; Bs[lk + 1][lr] = vb.y;
        Bs[lk + 2][lr] = vb.z; Bs[lk + 3][lr] = vb.w;
        __syncthreads();
        #pragma unroll
        for (int kk = 0; kk < 8; kk++) {
            float a[8], b[8];
            *(float4*)&a[0] = *(const float4*)&As[kk][ty * 8];
            *(float4*)&a[4] = *(const float4*)&As[kk][ty * 8 + 4];
            *(float4*)&b[0] = *(const float4*)&Bs[kk][tx * 8];
            *(float4*)&b[4] = *(const float4*)&Bs[kk][tx * 8 + 4];
            #pragma unroll
            for (int i = 0; i < 8; i++)
                #pragma unroll
                for (int j = 0; j < 8; j++)
                    acc[i][j] = fmaf(a[i], b[j], acc[i][j]);
        }
        __syncthreads();
    }

    #pragma unroll
    for (int i = 0; i < 8; i++) {
        int m = m0 + ty * 8 + i;
        if (m >= M) continue;
        #pragma unroll
        for (int j = 0; j < 8; j++) {
            int n = n0 + tx * 8 + j;
            if (n >= N) continue;
            size_t idx = (size_t)m * N + n;
            if (ACC) C[idx] += acc[i][j];
            else     C[idx]  = acc[i][j];
        }
    }
}

// ---------------- precompute -exp(A_log) for the layer ----------------
__global__ void k_aneg(const float* __restrict__ A_log) {
    int i = blockIdx.x * 256 + threadIdx.x;
    if (i < EINNER * NSTATE) g_Aneg[i] = -__expf(A_log[i]);
}

// ---------------- causal depthwise conv (width 4) + SiLU ----------------
__global__ void k_conv(const float* __restrict__ cw, const float* __restrict__ cb) {
    int g = blockIdx.x * 256 + threadIdx.x;
    if (g >= EINNER * LSEQ) return;
    int i = g % EINNER;
    int l = g / EINNER;
    float acc = cb[i];
    float4 w4 = *(const float4*)(cw + i * 4);
    float wk[4] = { w4.x, w4.y, w4.z, w4.w };
    #pragma unroll
    for (int k = 0; k < 4; k++) {
        int ll = l - 3 + k;
        if (ll >= 0) acc += g_xz[(size_t)ll * 2 * EINNER + i] * wk[k];
    }
    float sg = 1.f / (1.f + __expf(-acc));
    g_xc[(size_t)l * EINNER + i] = acc * sg;
}

// ---------------- x_proj: proj[l,p] = sum_i xc[l,i] * xw[p,i] ----------------
__global__ void k_xproj(const float* __restrict__ xw) {
    __shared__ float xs[EINNER];
    int l = blockIdx.x;
    for (int i = threadIdx.x; i < EINNER; i += 256)
        xs[i] = g_xc[(size_t)l * EINNER + i];
    __syncthreads();
    int warp = threadIdx.x >> 5, lane = threadIdx.x & 31;
    for (int p = warp; p < PROJW; p += 8) {
        const float* w = xw + (size_t)p * EINNER;
        float s = 0.f;
        for (int i = lane; i < EINNER; i += 32) s = fmaf(xs[i], w[i], s);
        #pragma unroll
        for (int o = 16; o; o >>= 1) s += __shfl_xor_sync(0xffffffffu, s, o);
        if (lane == 0) g_proj[l * PROJW + p] = s;
    }
}

// ---------------- dt = softplus(dt_part @ dtw^T + dtb) ----------------
__global__ void k_dt(const float* __restrict__ dtw, const float* __restrict__ dtb) {
    __shared__ float pr[DTR];
    int l = blockIdx.x;
    if (threadIdx.x < DTR) pr[threadIdx.x] = g_proj[l * PROJW + threadIdx.x];
    __syncthreads();
    for (int i = threadIdx.x; i < EINNER; i += 256) {
        float s = dtb[i];
        const float* w = dtw + (size_t)i * DTR;
        #pragma unroll
        for (int r = 0; r < DTR; r++) s = fmaf(pr[r], w[r], s);
        float sp = (s > 20.f) ? s : log1pf(__expf(s));
        g_dt[(size_t)l * EINNER + i] = sp;
    }
}

// ---------------- scan pass A: per-chunk (prodA, partialB) ----------------
__global__ void k_scanA() {
    int i = blockIdx.x * 128 + threadIdx.x;  // channel
    int c = blockIdx.y;                      // chunk
    float Aa[NSTATE], pA[NSTATE], pB[NSTATE];
    #pragma unroll
    for (int s = 0; s < NSTATE; s++) {
        Aa[s] = g_Aneg[i * NSTATE + s];
        pA[s] = 1.f; pB[s] = 0.f;
    }
    int l0 = c * CLEN;
    for (int l = l0; l < l0 + CLEN; l++) {
        float dt  = g_dt[(size_t)l * EINNER + i];
        float xv  = g_xc[(size_t)l * EINNER + i];
        float dtx = dt * xv;
        const float* Brow = g_proj + l * PROJW + DTR;
        #pragma unroll
        for (int s = 0; s < NSTATE; s++) {
            float da = __expf(dt * Aa[s]);
            pA[s] *= da;
            pB[s] = fmaf(da, pB[s], dtx * Brow[s]);
        }
    }
    size_t base = ((size_t)c * EINNER + i) * NSTATE;
    #pragma unroll
    for (int s = 0; s < NSTATE; s++) { g_cA[base + s] = pA[s]; g_cB[base + s] = pB[s]; }
}

// ---------------- scan pass B: sequential over chunks ----------------
__global__ void k_scanB() {
    int idx = blockIdx.x * 256 + threadIdx.x;   // over EINNER*NSTATE
    if (idx >= EINNER * NSTATE) return;
    float st = 0.f;
    #pragma unroll
    for (int c = 0; c < NCHUNK; c++) {
        size_t off = (size_t)c * EINNER * NSTATE + idx;
        g_ini[off] = st;
        st = fmaf(g_cA[off], st, g_cB[off]);
    }
}

// ---------------- scan pass C: replay chunks with init state; y, gating ----------------
__global__ void k_scanC(const float* __restrict__ Dp) {
    int i = blockIdx.x * 128 + threadIdx.x;
    int c = blockIdx.y;
    float Aa[NSTATE], hst[NSTATE];
    size_t base = ((size_t)c * EINNER + i) * NSTATE;
    #pragma unroll
    for (int s = 0; s < NSTATE; s++) {
        Aa[s]  = g_Aneg[i * NSTATE + s];
        hst[s] = g_ini[base + s];
    }
    float dpi = Dp[i];
    int l0 = c * CLEN;
    for (int l = l0; l < l0 + CLEN; l++) {
        float dt  = g_dt[(size_t)l * EINNER + i];
        float xv  = g_xc[(size_t)l * EINNER + i];
        float dtx = dt * xv;
        const float* Brow = g_proj + l * PROJW + DTR;
        const float* Crow = Brow + NSTATE;
        float y = 0.f;
        #pragma unroll
        for (int s = 0; s < NSTATE; s++) {
            float da = __expf(dt * Aa[s]);
            hst[s] = fmaf(da, hst[s], dtx * Brow[s]);
            y = fmaf(hst[s], Crow[s], y);
        }
        y = fmaf(xv, dpi, y);
        float z = g_xz[(size_t)l * 2 * EINNER + EINNER + i];
        float sil = z / (1.f + __expf(-z));
        g_y[(size_t)l * EINNER + i] = y * sil;
    }
}

// ---------------- tail zero (extra output elements beyond logits) ----------------
__global__ void k_tail(float* out, int start, int total) {
    int i = start + blockIdx.x * 256 + threadIdx.x;
    if (i < total) out[i] = 0.f;
}

// ---------------- host launcher ----------------
extern "C" void kernel_launch(void* const* d_in, const int* in_sizes, int n_in,
                              void* d_out, int out_size) {
    const int*   x     = (const int*)  d_in[0];
    const float* embed = (const float*)d_in[1];
    const float* normw = (const float*)d_in[2];
    const float* inw   = (const float*)d_in[3];
    const float* cw    = (const float*)d_in[4];
    const float* cb    = (const float*)d_in[5];
    const float* xw    = (const float*)d_in[6];
    const float* dtw   = (const float*)d_in[7];
    const float* dtb   = (const float*)d_in[8];
    const float* Alog  = (const float*)d_in[9];
    const float* Dp    = (const float*)d_in[10];
    const float* ow    = (const float*)d_in[11];
    const float* nfw   = (const float*)d_in[12];
    float* out = (float*)d_out;

    void *p_h, *p_hn, *p_xz, *p_xc, *p_y;
    cudaGetSymbolAddress(&p_h,  g_h);
    cudaGetSymbolAddress(&p_hn, g_hn);
    cudaGetSymbolAddress(&p_xz, g_xz);
    cudaGetSymbolAddress(&p_xc, g_xc);
    cudaGetSymbolAddress(&p_y,  g_y);

    k_embed<<<LSEQ, 256>>>(x, embed);

    for (int layer = 0; layer < NLAYER; layer++) {
        const float* l_norm = normw + (size_t)layer * DM;
        const float* l_inw  = inw   + (size_t)layer * 2 * EINNER * DM;
        const float* l_cw   = cw    + (size_t)layer * EINNER * 4;
        const float* l_cb   = cb    + (size_t)layer * EINNER;
        const float* l_xw   = xw    + (size_t)layer * PROJW * EINNER;
        const float* l_dtw  = dtw   + (size_t)layer * EINNER * DTR;
        const float* l_dtb  = dtb   + (size_t)layer * EINNER;
        const float* l_Al   = Alog  + (size_t)layer * EINNER * NSTATE;
        const float* l_Dp   = Dp    + (size_t)layer * EINNER;
        const float* l_ow   = ow    + (size_t)layer * DM * EINNER;

        k_rmsnorm<<<LSEQ, 256>>>(l_norm);

        // xz = hn @ in_proj^T : [1024, 3072]
        {
            dim3 grid((2 * EINNER + 127) / 128, (LSEQ + 127) / 128);
            k_sgemm<false><<<grid, 256>>>((const float*)p_hn, l_inw, (float*)p_xz,
                                          LSEQ, 2 * EINNER, DM);
        }

        // conv + silu
        k_conv<<<(EINNER * LSEQ + 255) / 256, 256>>>(l_cw, l_cb);

        k_xproj<<<LSEQ, 256>>>(l_xw);
        k_dt<<<LSEQ, 256>>>(l_dtw, l_dtb);

        // chunked selective scan
        k_aneg<<<(EINNER * NSTATE + 255) / 256, 256>>>(l_Al);
        {
            dim3 grid(EINNER / 128, NCHUNK);
            k_scanA<<<grid, 128>>>();
            k_scanB<<<(EINNER * NSTATE + 255) / 256, 256>>>();
            k_scanC<<<grid, 128>>>(l_Dp);
        }

        // h += y @ out_proj^T : [1024, 768]
        {
            dim3 grid((DM + 127) / 128, (LSEQ + 127) / 128);
            k_sgemm<true><<<grid, 256>>>((const float*)p_y, l_ow, (float*)p_h,
                                         LSEQ, DM, EINNER);
        }
    }

    // final rmsnorm + logits
    k_rmsnorm<<<LSEQ, 256>>>(nfw);
    {
        dim3 grid((VOC + 127) / 128, (LSEQ + 127) / 128);
        k_sgemm<false><<<grid, 256>>>((const float*)p_hn, embed, out,
                                      LSEQ, VOC, DM);
    }

    long long logits_n = (long long)LSEQ * VOC;
    if ((long long)out_size > logits_n) {
        int tail = (int)((long long)out_size - logits_n);
        k_tail<<<(tail + 255) / 256, 256>>>(out, (int)logits_n, out_size);
    }
}

// round 6
// speedup vs baseline: 1.6020x; 1.6020x over previous
#include <cuda_runtime.h>
#include <cuda_bf16.h>
#include <stdint.h>
#include <math.h>

// ---------------- problem constants ----------------
#define LSEQ   1024
#define DM     768
#define EINNER 1536
#define NSTATE 16
#define DTR    48
#define VOC    50257
#define PROJW  80          // DTR + 2*NSTATE
#define NCHUNK 16
#define CLEN   64          // LSEQ / NCHUNK
#define NLAYER 4

// ---------------- scratch (static device globals; no allocation) ----------------
__device__ float g_h   [LSEQ * DM];
__device__ float g_hn  [LSEQ * DM];
__device__ float g_xz  [LSEQ * 2 * EINNER];
__device__ float g_xc  [LSEQ * EINNER];
__device__ float g_proj[LSEQ * PROJW];
__device__ float g_dt  [LSEQ * EINNER];
__device__ float g_y   [LSEQ * EINNER];
__device__ float g_cA  [NCHUNK * EINNER * NSTATE];
__device__ float g_cB  [NCHUNK * EINNER * NSTATE];
__device__ float g_ini [NCHUNK * EINNER * NSTATE];
__device__ float g_Aneg[EINNER * NSTATE];

// bf16 split scratch
__device__ __nv_bfloat16 s_eh[VOC * DM];            // embed hi
__device__ __nv_bfloat16 s_el[VOC * DM];            // embed lo
__device__ __nv_bfloat16 s_wh[2 * EINNER * DM];     // weight hi (reused)
__device__ __nv_bfloat16 s_wl[2 * EINNER * DM];     // weight lo
__device__ __nv_bfloat16 s_ah[LSEQ * EINNER];       // activation hi (reused)
__device__ __nv_bfloat16 s_al[LSEQ * EINNER];       // activation lo

// ---------------- embedding gather ----------------
__global__ void k_embed(const int* __restrict__ x, const float* __restrict__ embed) {
    int l = blockIdx.x;
    int t = x[l];
    for (int d = threadIdx.x; d < DM; d += blockDim.x)
        g_h[l * DM + d] = embed[(size_t)t * DM + d];
}

// ---------------- rmsnorm: g_hn = rmsnorm(g_h, w) ----------------
__global__ void k_rmsnorm(const float* __restrict__ w) {
    __shared__ float red[8];
    int l = blockIdx.x;
    float s = 0.f;
    for (int d = threadIdx.x; d < DM; d += 256) {
        float v = g_h[l * DM + d];
        s += v * v;
    }
    #pragma unroll
    for (int o = 16; o; o >>= 1) s += __shfl_xor_sync(0xffffffffu, s, o);
    if ((threadIdx.x & 31) == 0) red[threadIdx.x >> 5] = s;
    __syncthreads();
    if (threadIdx.x == 0) {
        float t = 0.f;
        #pragma unroll
        for (int i = 0; i < 8; i++) t += red[i];
        red[0] = rsqrtf(t / DM + 1e-5f);
    }
    __syncthreads();
    float r = red[0];
    for (int d = threadIdx.x; d < DM; d += 256)
        g_hn[l * DM + d] = g_h[l * DM + d] * r * w[d];
}

// ---------------- fp32 -> bf16 (hi, lo) split ----------------
__global__ void k_split(const float* __restrict__ src,
                        __nv_bfloat16* __restrict__ hi,
                        __nv_bfloat16* __restrict__ lo, int n) {
    int i = blockIdx.x * 256 + threadIdx.x;
    if (i >= n) return;
    float x = src[i];
    __nv_bfloat16 h = __float2bfloat16_rn(x);
    float r = x - __bfloat162float(h);
    hi[i] = h;
    lo[i] = __float2bfloat16_rn(r);
}

// ---------------- tensor-core GEMM: C[M,N] (+)= (Ahi+Alo)[M,K] * (Bhi+Blo)[N,K]^T ----------------
// bf16x3 split: Ahi*Bhi + Alo*Bhi + Ahi*Blo. 128x128x32 tile, cp.async 2-stage,
// 256 threads / 8 warps (2x4), warp tile 64x32, mma.sync m16n8k16.
// Requires: M % 128 == 0, K % 32 == 0 (true here). N guarded.
#define BM 128
#define BN 128
#define BK 32
#define SSTR 40   // padded bf16 row stride in smem

template<bool ACC>
__global__ void __launch_bounds__(256)
k_bmm(const __nv_bfloat16* __restrict__ Ahi, const __nv_bfloat16* __restrict__ Alo,
      const __nv_bfloat16* __restrict__ Bhi, const __nv_bfloat16* __restrict__ Blo,
      float* __restrict__ C, int M, int N, int K) {
    __shared__ __align__(16) __nv_bfloat16 sA[2][BM * SSTR];
    __shared__ __align__(16) __nv_bfloat16 sB[2][BN * SSTR];

    int tid  = threadIdx.x;
    int lane = tid & 31;
    int warp = tid >> 5;
    int wm = warp >> 2, wn = warp & 3;         // 2 x 4 warp grid
    int m0 = blockIdx.y * BM, n0 = blockIdx.x * BN;

    int tilesK = K / BK;
    int TT = 3 * tilesK;

    float acc[4][4][4];
    #pragma unroll
    for (int i = 0; i < 4; i++)
        #pragma unroll
        for (int j = 0; j < 4; j++)
            #pragma unroll
            for (int r = 0; r < 4; r++) acc[i][j][r] = 0.f;

    auto issue_tile = [&](int t, int buf) {
        int phase = t / tilesK;
        int k0 = (t - phase * tilesK) * BK;
        const __nv_bfloat16* Ap = (phase == 1) ? Alo : Ahi;
        const __nv_bfloat16* Bp = (phase == 2) ? Blo : Bhi;
        #pragma unroll
        for (int u = 0; u < 2; u++) {
            int id  = tid + u * 256;
            int row = id >> 2;
            int ch  = (id & 3) * 8;
            {
                const void* g = (const void*)(Ap + (size_t)(m0 + row) * K + k0 + ch);
                unsigned int s = (unsigned int)__cvta_generic_to_shared(&sA[buf][row * SSTR + ch]);
                asm volatile("cp.async.cg.shared.global [%0], [%1], 16;" :: "r"(s), "l"(g));
            }
            {
                int gn = n0 + row;
                int sz = (gn < N) ? 16 : 0;
                int gr = (gn < N) ? gn : 0;
                const void* g = (const void*)(Bp + (size_t)gr * K + k0 + ch);
                unsigned int s = (unsigned int)__cvta_generic_to_shared(&sB[buf][row * SSTR + ch]);
                asm volatile("cp.async.cg.shared.global [%0], [%1], 16, %2;" :: "r"(s), "l"(g), "r"(sz));
            }
        }
        asm volatile("cp.async.commit_group;");
    };

    issue_tile(0, 0);

    for (int t = 0; t < TT; t++) {
        int buf = t & 1;
        if (t + 1 < TT) {
            issue_tile(t + 1, buf ^ 1);
            asm volatile("cp.async.wait_group 1;");
        } else {
            asm volatile("cp.async.wait_group 0;");
        }
        __syncthreads();

        #pragma unroll
        for (int step = 0; step < 2; step++) {
            int kk = step * 16;
            int l16 = lane & 15;
            unsigned int bfr[4][2];
            #pragma unroll
            for (int nt = 0; nt < 4; nt++) {
                int rown = wn * 32 + nt * 8 + (l16 & 7);
                int kc = kk + (l16 >> 3) * 8;
                unsigned int s = (unsigned int)__cvta_generic_to_shared(&sB[buf][rown * SSTR + kc]);
                asm volatile("ldmatrix.sync.aligned.m8n8.x2.shared.b16 {%0,%1}, [%2];"
                             : "=r"(bfr[nt][0]), "=r"(bfr[nt][1]) : "r"(s));
            }
            #pragma unroll
            for (int mt = 0; mt < 4; mt++) {
                unsigned int a0, a1, a2, a3;
                int rowm = wm * 64 + mt * 16 + l16;
                int kc = kk + (lane >> 4) * 8;
                unsigned int s = (unsigned int)__cvta_generic_to_shared(&sA[buf][rowm * SSTR + kc]);
                asm volatile("ldmatrix.sync.aligned.m8n8.x4.shared.b16 {%0,%1,%2,%3}, [%4];"
                             : "=r"(a0), "=r"(a1), "=r"(a2), "=r"(a3) : "r"(s));
                #pragma unroll
                for (int nt = 0; nt < 4; nt++) {
                    asm volatile(
                        "mma.sync.aligned.m16n8k16.row.col.f32.bf16.bf16.f32 "
                        "{%0,%1,%2,%3}, {%4,%5,%6,%7}, {%8,%9}, {%0,%1,%2,%3};"
                        : "+f"(acc[mt][nt][0]), "+f"(acc[mt][nt][1]),
                          "+f"(acc[mt][nt][2]), "+f"(acc[mt][nt][3])
                        : "r"(a0), "r"(a1), "r"(a2), "r"(a3),
                          "r"(bfr[nt][0]), "r"(bfr[nt][1]));
                }
            }
        }
        __syncthreads();
    }

    // epilogue
    int grp = lane >> 2, tig = lane & 3;
    #pragma unroll
    for (int mt = 0; mt < 4; mt++) {
        int r0 = m0 + wm * 64 + mt * 16 + grp;
        #pragma unroll
        for (int nt = 0; nt < 4; nt++) {
            int c0 = n0 + wn * 32 + nt * 8 + tig * 2;
            if (c0 < N) {
                size_t i00 = (size_t)r0 * N + c0;
                size_t i10 = (size_t)(r0 + 8) * N + c0;
                if (ACC) { C[i00] += acc[mt][nt][0]; C[i10] += acc[mt][nt][2]; }
                else     { C[i00]  = acc[mt][nt][0]; C[i10]  = acc[mt][nt][2]; }
                if (c0 + 1 < N) {
                    if (ACC) { C[i00 + 1] += acc[mt][nt][1]; C[i10 + 1] += acc[mt][nt][3]; }
                    else     { C[i00 + 1]  = acc[mt][nt][1]; C[i10 + 1]  = acc[mt][nt][3]; }
                }
            }
        }
    }
}

// ---------------- precompute -exp(A_log) for the layer ----------------
__global__ void k_aneg(const float* __restrict__ A_log) {
    int i = blockIdx.x * 256 + threadIdx.x;
    if (i < EINNER * NSTATE) g_Aneg[i] = -__expf(A_log[i]);
}

// ---------------- causal depthwise conv (width 4) + SiLU ----------------
__global__ void k_conv(const float* __restrict__ cw, const float* __restrict__ cb) {
    int g = blockIdx.x * 256 + threadIdx.x;
    if (g >= EINNER * LSEQ) return;
    int i = g % EINNER;
    int l = g / EINNER;
    float acc = cb[i];
    float4 w4 = *(const float4*)(cw + i * 4);
    float wk[4] = { w4.x, w4.y, w4.z, w4.w };
    #pragma unroll
    for (int k = 0; k < 4; k++) {
        int ll = l - 3 + k;
        if (ll >= 0) acc += g_xz[(size_t)ll * 2 * EINNER + i] * wk[k];
    }
    float sg = 1.f / (1.f + __expf(-acc));
    g_xc[(size_t)l * EINNER + i] = acc * sg;
}

// ---------------- x_proj: proj[l,p] = sum_i xc[l,i] * xw[p,i] ----------------
__global__ void k_xproj(const float* __restrict__ xw) {
    __shared__ float xs[EINNER];
    int l = blockIdx.x;
    for (int i = threadIdx.x; i < EINNER; i += 256)
        xs[i] = g_xc[(size_t)l * EINNER + i];
    __syncthreads();
    int warp = threadIdx.x >> 5, lane = threadIdx.x & 31;
    for (int p = warp; p < PROJW; p += 8) {
        const float* w = xw + (size_t)p * EINNER;
        float s = 0.f;
        for (int i = lane; i < EINNER; i += 32) s = fmaf(xs[i], w[i], s);
        #pragma unroll
        for (int o = 16; o; o >>= 1) s += __shfl_xor_sync(0xffffffffu, s, o);
        if (lane == 0) g_proj[l * PROJW + p] = s;
    }
}

// ---------------- dt = softplus(dt_part @ dtw^T + dtb) ----------------
__global__ void k_dt(const float* __restrict__ dtw, const float* __restrict__ dtb) {
    __shared__ float pr[DTR];
    int l = blockIdx.x;
    if (threadIdx.x < DTR) pr[threadIdx.x] = g_proj[l * PROJW + threadIdx.x];
    __syncthreads();
    for (int i = threadIdx.x; i < EINNER; i += 256) {
        float s = dtb[i];
        const float* w = dtw + (size_t)i * DTR;
        #pragma unroll
        for (int r = 0; r < DTR; r++) s = fmaf(pr[r], w[r], s);
        float sp = (s > 20.f) ? s : log1pf(__expf(s));
        g_dt[(size_t)l * EINNER + i] = sp;
    }
}

// ---------------- scan pass A: per-chunk (prodA, partialB) ----------------
__global__ void k_scanA() {
    int i = blockIdx.x * 128 + threadIdx.x;
    int c = blockIdx.y;
    float Aa[NSTATE], pA[NSTATE], pB[NSTATE];
    #pragma unroll
    for (int s = 0; s < NSTATE; s++) {
        Aa[s] = g_Aneg[i * NSTATE + s];
        pA[s] = 1.f; pB[s] = 0.f;
    }
    int l0 = c * CLEN;
    for (int l = l0; l < l0 + CLEN; l++) {
        float dt  = g_dt[(size_t)l * EINNER + i];
        float xv  = g_xc[(size_t)l * EINNER + i];
        float dtx = dt * xv;
        const float* Brow = g_proj + l * PROJW + DTR;
        #pragma unroll
        for (int s = 0; s < NSTATE; s++) {
            float da = __expf(dt * Aa[s]);
            pA[s] *= da;
            pB[s] = fmaf(da, pB[s], dtx * Brow[s]);
        }
    }
    size_t base = ((size_t)c * EINNER + i) * NSTATE;
    #pragma unroll
    for (int s = 0; s < NSTATE; s++) { g_cA[base + s] = pA[s]; g_cB[base + s] = pB[s]; }
}

// ---------------- scan pass B: sequential over chunks ----------------
__global__ void k_scanB() {
    int idx = blockIdx.x * 256 + threadIdx.x;
    if (idx >= EINNER * NSTATE) return;
    float st = 0.f;
    #pragma unroll
    for (int c = 0; c < NCHUNK; c++) {
        size_t off = (size_t)c * EINNER * NSTATE + idx;
        g_ini[off] = st;
        st = fmaf(g_cA[off], st, g_cB[off]);
    }
}

// ---------------- scan pass C: replay with init state; y, gating ----------------
__global__ void k_scanC(const float* __restrict__ Dp) {
    int i = blockIdx.x * 128 + threadIdx.x;
    int c = blockIdx.y;
    float Aa[NSTATE], hst[NSTATE];
    size_t base = ((size_t)c * EINNER + i) * NSTATE;
    #pragma unroll
    for (int s = 0; s < NSTATE; s++) {
        Aa[s]  = g_Aneg[i * NSTATE + s];
        hst[s] = g_ini[base + s];
    }
    float dpi = Dp[i];
    int l0 = c * CLEN;
    for (int l = l0; l < l0 + CLEN; l++) {
        float dt  = g_dt[(size_t)l * EINNER + i];
        float xv  = g_xc[(size_t)l * EINNER + i];
        float dtx = dt * xv;
        const float* Brow = g_proj + l * PROJW + DTR;
        const float* Crow = Brow + NSTATE;
        float y = 0.f;
        #pragma unroll
        for (int s = 0; s < NSTATE; s++) {
            float da = __expf(dt * Aa[s]);
            hst[s] = fmaf(da, hst[s], dtx * Brow[s]);
            y = fmaf(hst[s], Crow[s], y);
        }
        y = fmaf(xv, dpi, y);
        float z = g_xz[(size_t)l * 2 * EINNER + EINNER + i];
        float sil = z / (1.f + __expf(-z));
        g_y[(size_t)l * EINNER + i] = y * sil;
    }
}

// ---------------- tail zero ----------------
__global__ void k_tail(float* out, int start, int total) {
    int i = start + blockIdx.x * 256 + threadIdx.x;
    if (i < total) out[i] = 0.f;
}

// ---------------- host launcher ----------------
extern "C" void kernel_launch(void* const* d_in, const int* in_sizes, int n_in,
                              void* d_out, int out_size) {
    const int*   x     = (const int*)  d_in[0];
    const float* embed = (const float*)d_in[1];
    const float* normw = (const float*)d_in[2];
    const float* inw   = (const float*)d_in[3];
    const float* cw    = (const float*)d_in[4];
    const float* cb    = (const float*)d_in[5];
    const float* xw    = (const float*)d_in[6];
    const float* dtw   = (const float*)d_in[7];
    const float* dtb   = (const float*)d_in[8];
    const float* Alog  = (const float*)d_in[9];
    const float* Dp    = (const float*)d_in[10];
    const float* ow    = (const float*)d_in[11];
    const float* nfw   = (const float*)d_in[12];
    float* out = (float*)d_out;

    void *p_h, *p_hn, *p_xz, *p_y;
    void *p_eh, *p_el, *p_wh, *p_wl, *p_ah, *p_al;
    cudaGetSymbolAddress(&p_h,  g_h);
    cudaGetSymbolAddress(&p_hn, g_hn);
    cudaGetSymbolAddress(&p_xz, g_xz);
    cudaGetSymbolAddress(&p_y,  g_y);
    cudaGetSymbolAddress(&p_eh, s_eh);
    cudaGetSymbolAddress(&p_el, s_el);
    cudaGetSymbolAddress(&p_wh, s_wh);
    cudaGetSymbolAddress(&p_wl, s_wl);
    cudaGetSymbolAddress(&p_ah, s_ah);
    cudaGetSymbolAddress(&p_al, s_al);

    const __nv_bfloat16* eh = (const __nv_bfloat16*)p_eh;
    const __nv_bfloat16* el = (const __nv_bfloat16*)p_el;
    __nv_bfloat16* wh = (__nv_bfloat16*)p_wh;
    __nv_bfloat16* wl = (__nv_bfloat16*)p_wl;
    __nv_bfloat16* ah = (__nv_bfloat16*)p_ah;
    __nv_bfloat16* al = (__nv_bfloat16*)p_al;

    k_embed<<<LSEQ, 256>>>(x, embed);
    // split embed once (layer independent)
    k_split<<<(VOC * DM + 255) / 256, 256>>>(embed, (__nv_bfloat16*)p_eh,
                                             (__nv_bfloat16*)p_el, VOC * DM);

    for (int layer = 0; layer < NLAYER; layer++) {
        const float* l_norm = normw + (size_t)layer * DM;
        const float* l_inw  = inw   + (size_t)layer * 2 * EINNER * DM;
        const float* l_cw   = cw    + (size_t)layer * EINNER * 4;
        const float* l_cb   = cb    + (size_t)layer * EINNER;
        const float* l_xw   = xw    + (size_t)layer * PROJW * EINNER;
        const float* l_dtw  = dtw   + (size_t)layer * EINNER * DTR;
        const float* l_dtb  = dtb   + (size_t)layer * EINNER;
        const float* l_Al   = Alog  + (size_t)layer * EINNER * NSTATE;
        const float* l_Dp   = Dp    + (size_t)layer * EINNER;
        const float* l_ow   = ow    + (size_t)layer * DM * EINNER;

        k_rmsnorm<<<LSEQ, 256>>>(l_norm);

        // xz = hn @ in_proj^T : [1024, 3072], K=768
        k_split<<<(LSEQ * DM + 255) / 256, 256>>>((const float*)p_hn, ah, al, LSEQ * DM);
        k_split<<<(2 * EINNER * DM + 255) / 256, 256>>>(l_inw, wh, wl, 2 * EINNER * DM);
        {
            dim3 grid((2 * EINNER) / BN, LSEQ / BM);
            k_bmm<false><<<grid, 256>>>(ah, al, wh, wl, (float*)p_xz,
                                        LSEQ, 2 * EINNER, DM);
        }

        k_conv<<<(EINNER * LSEQ + 255) / 256, 256>>>(l_cw, l_cb);
        k_xproj<<<LSEQ, 256>>>(l_xw);
        k_dt<<<LSEQ, 256>>>(l_dtw, l_dtb);

        k_aneg<<<(EINNER * NSTATE + 255) / 256, 256>>>(l_Al);
        {
            dim3 grid(EINNER / 128, NCHUNK);
            k_scanA<<<grid, 128>>>();
            k_scanB<<<(EINNER * NSTATE + 255) / 256, 256>>>();
            k_scanC<<<grid, 128>>>(l_Dp);
        }

        // h += y @ out_proj^T : [1024, 768], K=1536
        k_split<<<(LSEQ * EINNER + 255) / 256, 256>>>((const float*)p_y, ah, al, LSEQ * EINNER);
        k_split<<<(DM * EINNER + 255) / 256, 256>>>(l_ow, wh, wl, DM * EINNER);
        {
            dim3 grid(DM / BN, LSEQ / BM);
            k_bmm<true><<<grid, 256>>>(ah, al, wh, wl, (float*)p_h,
                                       LSEQ, DM, EINNER);
        }
    }

    // final rmsnorm + logits
    k_rmsnorm<<<LSEQ, 256>>>(nfw);
    k_split<<<(LSEQ * DM + 255) / 256, 256>>>((const float*)p_hn, ah, al, LSEQ * DM);
    {
        dim3 grid((VOC + BN - 1) / BN, LSEQ / BM);
        k_bmm<false><<<grid, 256>>>(ah, al, eh, el, out,
                                    LSEQ, VOC, DM);
    }

    long long logits_n = (long long)LSEQ * VOC;
    if ((long long)out_size > logits_n) {
        int tail = (int)((long long)out_size - logits_n);
        k_tail<<<(tail + 255) / 256, 256>>>(out, (int)logits_n, out_size);
    }
}

// round 8
// speedup vs baseline: 1.7440x; 1.0887x over previous
#include <cuda_runtime.h>
#include <cuda_bf16.h>
#include <stdint.h>
#include <math.h>

// ---------------- problem constants ----------------
#define LSEQ   1024
#define DM     768
#define EINNER 1536
#define NSTATE 16
#define DTR    48
#define VOC    50257
#define PROJW  80          // DTR + 2*NSTATE
#define NCHUNK 16
#define CLEN   64          // LSEQ / NCHUNK
#define NLAYER 4

// ---------------- scratch (static device globals; no allocation) ----------------
__device__ float g_h   [LSEQ * DM];
__device__ float g_hn  [LSEQ * DM];
__device__ float g_xz  [LSEQ * 2 * EINNER];
__device__ float g_xc  [LSEQ * EINNER];
__device__ float g_proj[LSEQ * PROJW];
__device__ float g_dt  [LSEQ * EINNER];
__device__ float g_y   [LSEQ * EINNER];
__device__ float g_cA  [NCHUNK * EINNER * NSTATE];
__device__ float g_cB  [NCHUNK * EINNER * NSTATE];
__device__ float g_ini [NCHUNK * EINNER * NSTATE];
__device__ float g_Aneg[EINNER * NSTATE];

// bf16 split scratch
__device__ __nv_bfloat16 s_eh[VOC * DM];            // embed hi
__device__ __nv_bfloat16 s_el[VOC * DM];            // embed lo
__device__ __nv_bfloat16 s_wh[2 * EINNER * DM];     // weight hi (reused)
__device__ __nv_bfloat16 s_wl[2 * EINNER * DM];     // weight lo
__device__ __nv_bfloat16 s_ah[LSEQ * EINNER];       // activation hi (reused)
__device__ __nv_bfloat16 s_al[LSEQ * EINNER];       // activation lo

// ---------------- embedding gather ----------------
__global__ void k_embed(const int* __restrict__ x, const float* __restrict__ embed) {
    int l = blockIdx.x;
    int t = x[l];
    for (int d = threadIdx.x; d < DM; d += blockDim.x)
        g_h[l * DM + d] = embed[(size_t)t * DM + d];
}

// ---------------- rmsnorm ----------------
__global__ void k_rmsnorm(const float* __restrict__ w) {
    __shared__ float red[8];
    int l = blockIdx.x;
    float s = 0.f;
    for (int d = threadIdx.x; d < DM; d += 256) {
        float v = g_h[l * DM + d];
        s += v * v;
    }
    #pragma unroll
    for (int o = 16; o; o >>= 1) s += __shfl_xor_sync(0xffffffffu, s, o);
    if ((threadIdx.x & 31) == 0) red[threadIdx.x >> 5] = s;
    __syncthreads();
    if (threadIdx.x == 0) {
        float t = 0.f;
        #pragma unroll
        for (int i = 0; i < 8; i++) t += red[i];
        red[0] = rsqrtf(t / DM + 1e-5f);
    }
    __syncthreads();
    float r = red[0];
    for (int d = threadIdx.x; d < DM; d += 256)
        g_hn[l * DM + d] = g_h[l * DM + d] * r * w[d];
}

// ---------------- fp32 -> bf16 (hi, lo) split, 8 elems/thread vectorized ----------------
__device__ __forceinline__ unsigned pack_bf2(float a, float b) {
    __nv_bfloat162 t = __floats2bfloat162_rn(a, b);
    return *(unsigned*)&t;
}

__global__ void k_split8(const float4* __restrict__ src,
                         uint4* __restrict__ hi,
                         uint4* __restrict__ lo, int n8) {
    int i = blockIdx.x * 256 + threadIdx.x;
    if (i >= n8) return;
    float4 a = src[2 * i];
    float4 b = src[2 * i + 1];
    float v[8] = { a.x, a.y, a.z, a.w, b.x, b.y, b.z, b.w };
    float h[8], r[8];
    #pragma unroll
    for (int k = 0; k < 8; k++) {
        h[k] = __bfloat162float(__float2bfloat16_rn(v[k]));
        r[k] = v[k] - h[k];
    }
    hi[i] = make_uint4(pack_bf2(h[0], h[1]), pack_bf2(h[2], h[3]),
                       pack_bf2(h[4], h[5]), pack_bf2(h[6], h[7]));
    lo[i] = make_uint4(pack_bf2(r[0], r[1]), pack_bf2(r[2], r[3]),
                       pack_bf2(r[4], r[5]), pack_bf2(r[6], r[7]));
}

// ---------------- tensor-core GEMM, fused 3-term split in ONE K-pass ----------------
// C[M,N] (+)= Ahi*Bhi^T + Alo*Bhi^T + Ahi*Blo^T
// 128x128x32 tile, 4 slabs (Ahi,Alo,Bhi,Blo) double-buffered in dynamic smem,
// 256 threads / 8 warps (2x4), warp tile 64x32, mma.sync m16n8k16.
// grid.x = M tiles (fast axis -> co-resident blocks share B slab in L2), grid.y = N tiles.
#define BM 128
#define BN 128
#define BK 32
#define SSTR 40                 // padded bf16 row stride in smem
#define SLAB (128 * SSTR)       // one slab (elems)
#define SMEM_BYTES (8 * SLAB * 2)  // 4 arrays x 2 stages x bf16

template<bool ACC>
__global__ void __launch_bounds__(256)
k_bmm(const __nv_bfloat16* __restrict__ Ahi, const __nv_bfloat16* __restrict__ Alo,
      const __nv_bfloat16* __restrict__ Bhi, const __nv_bfloat16* __restrict__ Blo,
      float* __restrict__ C, int M, int N, int K) {
    extern __shared__ __align__(16) __nv_bfloat16 dsm[];
    __nv_bfloat16* sAh = dsm;
    __nv_bfloat16* sAl = dsm + 2 * SLAB;
    __nv_bfloat16* sBh = dsm + 4 * SLAB;
    __nv_bfloat16* sBl = dsm + 6 * SLAB;

    int tid  = threadIdx.x;
    int lane = tid & 31;
    int warp = tid >> 5;
    int wm = warp >> 2, wn = warp & 3;
    int m0 = blockIdx.x * BM, n0 = blockIdx.y * BN;

    int tilesK = K / BK;

    float acc[4][4][4];
    #pragma unroll
    for (int i = 0; i < 4; i++)
        #pragma unroll
        for (int j = 0; j < 4; j++)
            #pragma unroll
            for (int r = 0; r < 4; r++) acc[i][j][r] = 0.f;

    auto issue_tile = [&](int kt, int buf) {
        int k0 = kt * BK;
        int boff = buf * SLAB;
        #pragma unroll
        for (int u = 0; u < 2; u++) {
            int id  = tid + u * 256;
            int row = id >> 2;
            int ch  = (id & 3) * 8;
            size_t ga = (size_t)(m0 + row) * K + k0 + ch;
            int so = boff + row * SSTR + ch;
            {
                unsigned int s = (unsigned int)__cvta_generic_to_shared(&sAh[so]);
                asm volatile("cp.async.cg.shared.global [%0], [%1], 16;" :: "r"(s), "l"((const void*)(Ahi + ga)));
            }
            {
                unsigned int s = (unsigned int)__cvta_generic_to_shared(&sAl[so]);
                asm volatile("cp.async.cg.shared.global [%0], [%1], 16;" :: "r"(s), "l"((const void*)(Alo + ga)));
            }
            int gn = n0 + row;
            int sz = (gn < N) ? 16 : 0;
            int gr = (gn < N) ? gn : 0;
            size_t gb = (size_t)gr * K + k0 + ch;
            {
                unsigned int s = (unsigned int)__cvta_generic_to_shared(&sBh[so]);
                asm volatile("cp.async.cg.shared.global [%0], [%1], 16, %2;" :: "r"(s), "l"((const void*)(Bhi + gb)), "r"(sz));
            }
            {
                unsigned int s = (unsigned int)__cvta_generic_to_shared(&sBl[so]);
                asm volatile("cp.async.cg.shared.global [%0], [%1], 16, %2;" :: "r"(s), "l"((const void*)(Blo + gb)), "r"(sz));
            }
        }
        asm volatile("cp.async.commit_group;");
    };

    issue_tile(0, 0);

    for (int kt = 0; kt < tilesK; kt++) {
        int buf = kt & 1;
        if (kt + 1 < tilesK) {
            issue_tile(kt + 1, buf ^ 1);
            asm volatile("cp.async.wait_group 1;");
        } else {
            asm volatile("cp.async.wait_group 0;");
        }
        __syncthreads();

        int boff = buf * SLAB;
        #pragma unroll
        for (int step = 0; step < 2; step++) {
            int kk = step * 16;
            int l16 = lane & 15;
            unsigned int bh[4][2], bl[4][2];
            #pragma unroll
            for (int nt = 0; nt < 4; nt++) {
                int rown = wn * 32 + nt * 8 + (l16 & 7);
                int kc = kk + (l16 >> 3) * 8;
                int so = boff + rown * SSTR + kc;
                unsigned int s1 = (unsigned int)__cvta_generic_to_shared(&sBh[so]);
                asm volatile("ldmatrix.sync.aligned.m8n8.x2.shared.b16 {%0,%1}, [%2];"
                             : "=r"(bh[nt][0]), "=r"(bh[nt][1]) : "r"(s1));
                unsigned int s2 = (unsigned int)__cvta_generic_to_shared(&sBl[so]);
                asm volatile("ldmatrix.sync.aligned.m8n8.x2.shared.b16 {%0,%1}, [%2];"
                             : "=r"(bl[nt][0]), "=r"(bl[nt][1]) : "r"(s2));
            }
            #pragma unroll
            for (int mt = 0; mt < 4; mt++) {
                int rowm = wm * 64 + mt * 16 + l16;
                int kc = kk + (lane >> 4) * 8;
                int so = boff + rowm * SSTR + kc;
                unsigned int ah0, ah1, ah2, ah3, al0, al1, al2, al3;
                unsigned int s1 = (unsigned int)__cvta_generic_to_shared(&sAh[so]);
                asm volatile("ldmatrix.sync.aligned.m8n8.x4.shared.b16 {%0,%1,%2,%3}, [%4];"
                             : "=r"(ah0), "=r"(ah1), "=r"(ah2), "=r"(ah3) : "r"(s1));
                unsigned int s2 = (unsigned int)__cvta_generic_to_shared(&sAl[so]);
                asm volatile("ldmatrix.sync.aligned.m8n8.x4.shared.b16 {%0,%1,%2,%3}, [%4];"
                             : "=r"(al0), "=r"(al1), "=r"(al2), "=r"(al3) : "r"(s2));
                #pragma unroll
                for (int nt = 0; nt < 4; nt++) {
                    asm volatile(
                        "mma.sync.aligned.m16n8k16.row.col.f32.bf16.bf16.f32 "
                        "{%0,%1,%2,%3}, {%4,%5,%6,%7}, {%8,%9}, {%0,%1,%2,%3};"
                        : "+f"(acc[mt][nt][0]), "+f"(acc[mt][nt][1]),
                          "+f"(acc[mt][nt][2]), "+f"(acc[mt][nt][3])
                        : "r"(ah0), "r"(ah1), "r"(ah2), "r"(ah3),
                          "r"(bh[nt][0]), "r"(bh[nt][1]));
                    asm volatile(
                        "mma.sync.aligned.m16n8k16.row.col.f32.bf16.bf16.f32 "
                        "{%0,%1,%2,%3}, {%4,%5,%6,%7}, {%8,%9}, {%0,%1,%2,%3};"
                        : "+f"(acc[mt][nt][0]), "+f"(acc[mt][nt][1]),
                          "+f"(acc[mt][nt][2]), "+f"(acc[mt][nt][3])
                        : "r"(al0), "r"(al1), "r"(al2), "r"(al3),
                          "r"(bh[nt][0]), "r"(bh[nt][1]));
                    asm volatile(
                        "mma.sync.aligned.m16n8k16.row.col.f32.bf16.bf16.f32 "
                        "{%0,%1,%2,%3}, {%4,%5,%6,%7}, {%8,%9}, {%0,%1,%2,%3};"
                        : "+f"(acc[mt][nt][0]), "+f"(acc[mt][nt][1]),
                          "+f"(acc[mt][nt][2]), "+f"(acc[mt][nt][3])
                        : "r"(ah0), "r"(ah1), "r"(ah2), "r"(ah3),
                          "r"(bl[nt][0]), "r"(bl[nt][1]));
                }
            }
        }
        __syncthreads();
    }

    // epilogue
    int grp = lane >> 2, tig = lane & 3;
    #pragma unroll
    for (int mt = 0; mt < 4; mt++) {
        int r0 = m0 + wm * 64 + mt * 16 + grp;
        #pragma unroll
        for (int nt = 0; nt < 4; nt++) {
            int c0 = n0 + wn * 32 + nt * 8 + tig * 2;
            if (c0 < N) {
                size_t i00 = (size_t)r0 * N + c0;
                size_t i10 = (size_t)(r0 + 8) * N + c0;
                if (ACC) { C[i00] += acc[mt][nt][0]; C[i10] += acc[mt][nt][2]; }
                else     { C[i00]  = acc[mt][nt][0]; C[i10]  = acc[mt][nt][2]; }
                if (c0 + 1 < N) {
                    if (ACC) { C[i00 + 1] += acc[mt][nt][1]; C[i10 + 1] += acc[mt][nt][3]; }
                    else     { C[i00 + 1]  = acc[mt][nt][1]; C[i10 + 1]  = acc[mt][nt][3]; }
                }
            }
        }
    }
}

// ---------------- precompute -exp(A_log) ----------------
__global__ void k_aneg(const float* __restrict__ A_log) {
    int i = blockIdx.x * 256 + threadIdx.x;
    if (i < EINNER * NSTATE) g_Aneg[i] = -__expf(A_log[i]);
}

// ---------------- causal depthwise conv (width 4) + SiLU ----------------
__global__ void k_conv(const float* __restrict__ cw, const float* __restrict__ cb) {
    int g = blockIdx.x * 256 + threadIdx.x;
    if (g >= EINNER * LSEQ) return;
    int i = g % EINNER;
    int l = g / EINNER;
    float acc = cb[i];
    float4 w4 = *(const float4*)(cw + i * 4);
    float wk[4] = { w4.x, w4.y, w4.z, w4.w };
    #pragma unroll
    for (int k = 0; k < 4; k++) {
        int ll = l - 3 + k;
        if (ll >= 0) acc += g_xz[(size_t)ll * 2 * EINNER + i] * wk[k];
    }
    float sg = 1.f / (1.f + __expf(-acc));
    g_xc[(size_t)l * EINNER + i] = acc * sg;
}

// ---------------- x_proj ----------------
__global__ void k_xproj(const float* __restrict__ xw) {
    __shared__ float xs[EINNER];
    int l = blockIdx.x;
    for (int i = threadIdx.x; i < EINNER; i += 256)
        xs[i] = g_xc[(size_t)l * EINNER + i];
    __syncthreads();
    int warp = threadIdx.x >> 5, lane = threadIdx.x & 31;
    for (int p = warp; p < PROJW; p += 8) {
        const float* w = xw + (size_t)p * EINNER;
        float s = 0.f;
        for (int i = lane; i < EINNER; i += 32) s = fmaf(xs[i], w[i], s);
        #pragma unroll
        for (int o = 16; o; o >>= 1) s += __shfl_xor_sync(0xffffffffu, s, o);
        if (lane == 0) g_proj[l * PROJW + p] = s;
    }
}

// ---------------- dt = softplus(dt_part @ dtw^T + dtb) ----------------
__global__ void k_dt(const float* __restrict__ dtw, const float* __restrict__ dtb) {
    __shared__ float pr[DTR];
    int l = blockIdx.x;
    if (threadIdx.x < DTR) pr[threadIdx.x] = g_proj[l * PROJW + threadIdx.x];
    __syncthreads();
    for (int i = threadIdx.x; i < EINNER; i += 256) {
        float s = dtb[i];
        const float* w = dtw + (size_t)i * DTR;
        #pragma unroll
        for (int r = 0; r < DTR; r++) s = fmaf(pr[r], w[r], s);
        float sp = (s > 20.f) ? s : log1pf(__expf(s));
        g_dt[(size_t)l * EINNER + i] = sp;
    }
}

// ---------------- scan pass A ----------------
__global__ void k_scanA() {
    int i = blockIdx.x * 128 + threadIdx.x;
    int c = blockIdx.y;
    float Aa[NSTATE], pA[NSTATE], pB[NSTATE];
    #pragma unroll
    for (int s = 0; s < NSTATE; s++) {
        Aa[s] = g_Aneg[i * NSTATE + s];
        pA[s] = 1.f; pB[s] = 0.f;
    }
    int l0 = c * CLEN;
    for (int l = l0; l < l0 + CLEN; l++) {
        float dt  = g_dt[(size_t)l * EINNER + i];
        float xv  = g_xc[(size_t)l * EINNER + i];
        float dtx = dt * xv;
        const float* Brow = g_proj + l * PROJW + DTR;
        #pragma unroll
        for (int s = 0; s < NSTATE; s++) {
            float da = __expf(dt * Aa[s]);
            pA[s] *= da;
            pB[s] = fmaf(da, pB[s], dtx * Brow[s]);
        }
    }
    size_t base = ((size_t)c * EINNER + i) * NSTATE;
    #pragma unroll
    for (int s = 0; s < NSTATE; s++) { g_cA[base + s] = pA[s]; g_cB[base + s] = pB[s]; }
}

// ---------------- scan pass B ----------------
__global__ void k_scanB() {
    int idx = blockIdx.x * 256 + threadIdx.x;
    if (idx >= EINNER * NSTATE) return;
    float st = 0.f;
    #pragma unroll
    for (int c = 0; c < NCHUNK; c++) {
        size_t off = (size_t)c * EINNER * NSTATE + idx;
        g_ini[off] = st;
        st = fmaf(g_cA[off], st, g_cB[off]);
    }
}

// ---------------- scan pass C ----------------
__global__ void k_scanC(const float* __restrict__ Dp) {
    int i = blockIdx.x * 128 + threadIdx.x;
    int c = blockIdx.y;
    float Aa[NSTATE], hst[NSTATE];
    size_t base = ((size_t)c * EINNER + i) * NSTATE;
    #pragma unroll
    for (int s = 0; s < NSTATE; s++) {
        Aa[s]  = g_Aneg[i * NSTATE + s];
        hst[s] = g_ini[base + s];
    }
    float dpi = Dp[i];
    int l0 = c * CLEN;
    for (int l = l0; l < l0 + CLEN; l++) {
        float dt  = g_dt[(size_t)l * EINNER + i];
        float xv  = g_xc[(size_t)l * EINNER + i];
        float dtx = dt * xv;
        const float* Brow = g_proj + l * PROJW + DTR;
        const float* Crow = Brow + NSTATE;
        float y = 0.f;
        #pragma unroll
        for (int s = 0; s < NSTATE; s++) {
            float da = __expf(dt * Aa[s]);
            hst[s] = fmaf(da, hst[s], dtx * Brow[s]);
            y = fmaf(hst[s], Crow[s], y);
        }
        y = fmaf(xv, dpi, y);
        float z = g_xz[(size_t)l * 2 * EINNER + EINNER + i];
        float sil = z / (1.f + __expf(-z));
        g_y[(size_t)l * EINNER + i] = y * sil;
    }
}

// ---------------- tail zero ----------------
__global__ void k_tail(float* out, int start, int total) {
    int i = start + blockIdx.x * 256 + threadIdx.x;
    if (i < total) out[i] = 0.f;
}

// ---------------- host launcher ----------------
static inline void split8(const void* src, void* hi, void* lo, int n) {
    int n8 = n / 8;
    k_split8<<<(n8 + 255) / 256, 256>>>((const float4*)src, (uint4*)hi, (uint4*)lo, n8);
}

extern "C" void kernel_launch(void* const* d_in, const int* in_sizes, int n_in,
                              void* d_out, int out_size) {
    const int*   x     = (const int*)  d_in[0];
    const float* embed = (const float*)d_in[1];
    const float* normw = (const float*)d_in[2];
    const float* inw   = (const float*)d_in[3];
    const float* cw    = (const float*)d_in[4];
    const float* cb    = (const float*)d_in[5];
    const float* xw    = (const float*)d_in[6];
    const float* dtw   = (const float*)d_in[7];
    const float* dtb   = (const float*)d_in[8];
    const float* Alog  = (const float*)d_in[9];
    const float* Dp    = (const float*)d_in[10];
    const float* ow    = (const float*)d_in[11];
    const float* nfw   = (const float*)d_in[12];
    float* out = (float*)d_out;

    cudaFuncSetAttribute(k_bmm<false>, cudaFuncAttributeMaxDynamicSharedMemorySize, SMEM_BYTES);
    cudaFuncSetAttribute(k_bmm<true>,  cudaFuncAttributeMaxDynamicSharedMemorySize, SMEM_BYTES);

    void *p_h, *p_hn, *p_xz, *p_y;
    void *p_eh, *p_el, *p_wh, *p_wl, *p_ah, *p_al;
    cudaGetSymbolAddress(&p_h,  g_h);
    cudaGetSymbolAddress(&p_hn, g_hn);
    cudaGetSymbolAddress(&p_xz, g_xz);
    cudaGetSymbolAddress(&p_y,  g_y);
    cudaGetSymbolAddress(&p_eh, s_eh);
    cudaGetSymbolAddress(&p_el, s_el);
    cudaGetSymbolAddress(&p_wh, s_wh);
    cudaGetSymbolAddress(&p_wl, s_wl);
    cudaGetSymbolAddress(&p_ah, s_ah);
    cudaGetSymbolAddress(&p_al, s_al);

    const __nv_bfloat16* eh = (const __nv_bfloat16*)p_eh;
    const __nv_bfloat16* el = (const __nv_bfloat16*)p_el;
    __nv_bfloat16* wh = (__nv_bfloat16*)p_wh;
    __nv_bfloat16* wl = (__nv_bfloat16*)p_wl;
    __nv_bfloat16* ah = (__nv_bfloat16*)p_ah;
    __nv_bfloat16* al = (__nv_bfloat16*)p_al;

    k_embed<<<LSEQ, 256>>>(x, embed);
    split8(embed, p_eh, p_el, VOC * DM);      // embed split once per call

    for (int layer = 0; layer < NLAYER; layer++) {
        const float* l_norm = normw + (size_t)layer * DM;
        const float* l_inw  = inw   + (size_t)layer * 2 * EINNER * DM;
        const float* l_cw   = cw    + (size_t)layer * EINNER * 4;
        const float* l_cb   = cb    + (size_t)layer * EINNER;
        const float* l_xw   = xw    + (size_t)layer * PROJW * EINNER;
        const float* l_dtw  = dtw   + (size_t)layer * EINNER * DTR;
        const float* l_dtb  = dtb   + (size_t)layer * EINNER;
        const float* l_Al   = Alog  + (size_t)layer * EINNER * NSTATE;
        const float* l_Dp   = Dp    + (size_t)layer * EINNER;
        const float* l_ow   = ow    + (size_t)layer * DM * EINNER;

        k_rmsnorm<<<LSEQ, 256>>>(l_norm);

        // xz = hn @ in_proj^T : [1024, 3072], K=768
        split8(p_hn, ah, al, LSEQ * DM);
        split8(l_inw, wh, wl, 2 * EINNER * DM);
        {
            dim3 grid(LSEQ / BM, (2 * EINNER) / BN);
            k_bmm<false><<<grid, 256, SMEM_BYTES>>>(ah, al, wh, wl, (float*)p_xz,
                                                    LSEQ, 2 * EINNER, DM);
        }

        k_conv<<<(EINNER * LSEQ + 255) / 256, 256>>>(l_cw, l_cb);
        k_xproj<<<LSEQ, 256>>>(l_xw);
        k_dt<<<LSEQ, 256>>>(l_dtw, l_dtb);

        k_aneg<<<(EINNER * NSTATE + 255) / 256, 256>>>(l_Al);
        {
            dim3 grid(EINNER / 128, NCHUNK);
            k_scanA<<<grid, 128>>>();
            k_scanB<<<(EINNER * NSTATE + 255) / 256, 256>>>();
            k_scanC<<<grid, 128>>>(l_Dp);
        }

        // h += y @ out_proj^T : [1024, 768], K=1536
        split8(p_y, ah, al, LSEQ * EINNER);
        split8(l_ow, wh, wl, DM * EINNER);
        {
            dim3 grid(LSEQ / BM, DM / BN);
            k_bmm<true><<<grid, 256, SMEM_BYTES>>>(ah, al, wh, wl, (float*)p_h,
                                                   LSEQ, DM, EINNER);
        }
    }

    // final rmsnorm + logits
    k_rmsnorm<<<LSEQ, 256>>>(nfw);
    split8(p_hn, ah, al, LSEQ * DM);
    {
        dim3 grid(LSEQ / BM, (VOC + BN - 1) / BN);
        k_bmm<false><<<grid, 256, SMEM_BYTES>>>(ah, al, eh, el, out,
                                                LSEQ, VOC, DM);
    }

    long long logits_n = (long long)LSEQ * VOC;
    if ((long long)out_size > logits_n) {
        int tail = (int)((long long)out_size - logits_n);
        k_tail<<<(tail + 255) / 256, 256>>>(out, (int)logits_n, out_size);
    }
}